// round 1
// baseline (speedup 1.0000x reference)
#include <cuda_runtime.h>

#define BATCH 8
#define HW 256
#define KK 13
#define HO 244   // 256 - 13 + 1

// Scratch (allocation-free rule: __device__ globals)
static __device__ float g_h1[(size_t)BATCH * 64 * HW * HW];   // conv1 out
static __device__ float g_h2[(size_t)BATCH * 64 * HW * HW];   // conv2 out
static __device__ float g_w [(size_t)BATCH * 169 * HO * HO];  // conv3 out (cropped)

// Direct 3x3 conv, SAME-style. Block = 16x16 output pixels x OCB output
// channels. Input channels staged through smem in chunks of CC.
// inOff shifts the input window (conv3 reads the interior at +6).
template <int CIN, int CC, int OCB, bool RELU>
__global__ void __launch_bounds__(256) conv3x3_kernel(
    const float* __restrict__ in, int inH, int inW,
    const float* __restrict__ Wt, const float* __restrict__ bias,
    float* __restrict__ out, int outH, int outW,
    int inOff, int OC)
{
    __shared__ float sIn[CC][18][18];
    __shared__ float sW[OCB][CC][9];

    const int tx = threadIdx.x, ty = threadIdx.y;
    const int tid = ty * 16 + tx;
    const int ocChunks = OC / OCB;
    const int b  = blockIdx.z / ocChunks;
    const int og = blockIdx.z % ocChunks;
    const int ocBase = og * OCB;
    const int x0 = blockIdx.x * 16;
    const int y0 = blockIdx.y * 16;
    const int ox = x0 + tx, oy = y0 + ty;

    float acc[OCB];
#pragma unroll
    for (int o = 0; o < OCB; ++o) acc[o] = 0.f;

    const float* inB = in + (size_t)b * CIN * inH * inW;

    for (int c0 = 0; c0 < CIN; c0 += CC) {
        // Stage input tile (with halo, zero-padded at borders)
        for (int idx = tid; idx < CC * 18 * 18; idx += 256) {
            int c  = idx / (18 * 18);
            int r  = idx % (18 * 18);
            int ry = r / 18, rx = r % 18;
            int iy = y0 + inOff + ry - 1;
            int ix = x0 + inOff + rx - 1;
            float v = 0.f;
            if (iy >= 0 && iy < inH && ix >= 0 && ix < inW)
                v = inB[((size_t)(c0 + c) * inH + iy) * inW + ix];
            sIn[c][ry][rx] = v;
        }
        // Stage weight chunk
        for (int idx = tid; idx < OCB * CC * 9; idx += 256) {
            int o = idx / (CC * 9);
            int r = idx % (CC * 9);
            int c = r / 9, t = r % 9;
            sW[o][c][t] = Wt[((size_t)(ocBase + o) * CIN + (c0 + c)) * 9 + t];
        }
        __syncthreads();

#pragma unroll
        for (int c = 0; c < CC; ++c) {
            float v[9];
#pragma unroll
            for (int u = 0; u < 3; ++u)
#pragma unroll
                for (int w = 0; w < 3; ++w)
                    v[u * 3 + w] = sIn[c][ty + u][tx + w];
#pragma unroll
            for (int o = 0; o < OCB; ++o) {
#pragma unroll
                for (int t = 0; t < 9; ++t)
                    acc[o] = fmaf(v[t], sW[o][c][t], acc[o]);
            }
        }
        __syncthreads();
    }

    if (ox < outW && oy < outH) {
        float* outB = out + ((size_t)b * OC + ocBase) * outH * outW
                          + (size_t)oy * outW + ox;
#pragma unroll
        for (int o = 0; o < OCB; ++o) {
            float r = acc[o] + bias[ocBase + o];
            if (RELU) r = fmaxf(r, 0.f);
            outB[(size_t)o * outH * outW] = r;
        }
    }
}

// y[b,i,j] = sum_{u,v} x[b, i+u, j+v] * w[b, u*13+v, i, j]
__global__ void __launch_bounds__(256) agg_kernel(
    const float* __restrict__ x, float* __restrict__ y)
{
    int id = blockIdx.x * 256 + threadIdx.x;
    if (id >= BATCH * HO * HO) return;
    int j = id % HO;
    int i = (id / HO) % HO;
    int b = id / (HO * HO);
    const float* xb = x + (size_t)b * HW * HW;
    const float* wb = g_w + (size_t)b * 169 * HO * HO + (size_t)i * HO + j;
    float acc = 0.f;
    for (int u = 0; u < KK; ++u) {
        const float* xr = xb + (size_t)(i + u) * HW + j;
#pragma unroll
        for (int v = 0; v < KK; ++v)
            acc = fmaf(xr[v], wb[(size_t)(u * KK + v) * HO * HO], acc);
    }
    y[id] = acc;
}

extern "C" void kernel_launch(void* const* d_in, const int* in_sizes, int n_in,
                              void* d_out, int out_size)
{
    const float* x  = (const float*)d_in[0];
    const float* W1 = (const float*)d_in[1];
    const float* b1 = (const float*)d_in[2];
    const float* W2 = (const float*)d_in[3];
    const float* b2 = (const float*)d_in[4];
    const float* W3 = (const float*)d_in[5];
    const float* b3 = (const float*)d_in[6];
    float* y = (float*)d_out;

    float *h1, *h2, *w;
    cudaGetSymbolAddress((void**)&h1, g_h1);
    cudaGetSymbolAddress((void**)&h2, g_h2);
    cudaGetSymbolAddress((void**)&w,  g_w);

    dim3 blk(16, 16);

    // conv1: 1 -> 64, relu
    conv3x3_kernel<1, 1, 16, true><<<dim3(16, 16, BATCH * 4), blk>>>(
        x, HW, HW, W1, b1, h1, HW, HW, 0, 64);

    // conv2: 64 -> 64, relu
    conv3x3_kernel<64, 8, 16, true><<<dim3(16, 16, BATCH * 4), blk>>>(
        h1, HW, HW, W2, b2, h2, HW, HW, 0, 64);

    // conv3: 64 -> 169, cropped interior only (244x244, input window +6,
    // always in-bounds)
    conv3x3_kernel<64, 8, 13, false><<<dim3(16, 16, BATCH * 13), blk>>>(
        h2, HW, HW, W3, b3, w, HO, HO, 6, 169);

    // final per-pixel 13x13 patch dot-product
    int n = BATCH * HO * HO;
    agg_kernel<<<(n + 255) / 256, 256>>>(x, y);
}